// round 8
// baseline (speedup 1.0000x reference)
#include <cuda_runtime.h>
#include <cstdint>

#define CIN   32
#define COUT  64
#define TT    8
#define DDIM  32
#define HDIM  64
#define WDIM  64

#define NKSG  108                      // 864 k / 8 per mma step

// ---------- smem layout ----------
#define TBL_OFF  0                     // 108 uint2 row-offset pairs (216 floats.. 216 u32)
#define TBL_SIZE 216                   // u32 words
#define XS_OFF   TBL_SIZE              // 216 (word offset)
#define XS_SIZE  (8 * 12 * 68)         // 6528 words : x chunk 8c x (3d x 4h) x 68w (tf32)
#define SMEM_WORDS (XS_OFF + XS_SIZE)  // 6744
#define SMEM_BYTES (SMEM_WORDS * 4)    // 26976 -> 2+ blocks/SM easily

// fused weight fragments w'[b][ot][ksg][lane][nf][r], tf32 (884736 B)
__device__ uint32_t g_wf[4 * 2 * NKSG * 32 * 8];

// ---------- helpers ----------
__device__ __forceinline__ uint32_t smem_u32(const void* p) {
    uint32_t a;
    asm("{ .reg .u64 t; cvta.to.shared.u64 t, %1; cvt.u32.u64 %0, t; }" : "=r"(a) : "l"(p));
    return a;
}
__device__ __forceinline__ uint32_t f2tf32(float x) {
    uint32_t r; asm("cvt.rna.tf32.f32 %0, %1;" : "=r"(r) : "f"(x)); return r;
}
__device__ __forceinline__ uint32_t lds32(uint32_t a) {
    uint32_t v; asm volatile("ld.shared.b32 %0, [%1];" : "=r"(v) : "r"(a)); return v;
}
__device__ __forceinline__ void lds64(uint32_t a, uint32_t& x, uint32_t& y) {
    asm volatile("ld.shared.v2.b32 {%0,%1}, [%2];" : "=r"(x), "=r"(y) : "r"(a));
}
__device__ __forceinline__ void sts32(uint32_t a, uint32_t v) {
    asm volatile("st.shared.b32 [%0], %1;" :: "r"(a), "r"(v));
}
__device__ __forceinline__ void mma_tf32(float* c,
                                         uint32_t a0, uint32_t a1, uint32_t a2, uint32_t a3,
                                         uint32_t b0, uint32_t b1) {
    asm volatile("mma.sync.aligned.m16n8k8.row.col.f32.tf32.tf32.f32 "
                 "{%0,%1,%2,%3}, {%4,%5,%6,%7}, {%8,%9}, {%0,%1,%2,%3};"
                 : "+f"(c[0]), "+f"(c[1]), "+f"(c[2]), "+f"(c[3])
                 : "r"(a0), "r"(a1), "r"(a2), "r"(a3), "r"(b0), "r"(b1));
}

// ---------- init: w'[b,o,c,s] = sum_t weight[o,c,t]*stencils[b,t,s], frag layout ----------
__global__ void init_wf_kernel(const float* __restrict__ weight,
                               const float* __restrict__ stencils) {
    int idx = blockIdx.x * 256 + threadIdx.x;   // 0 .. 221183
    int r    = idx & 1;
    int nf   = (idx >> 1) & 3;
    int lane = (idx >> 3) & 31;
    int ksg  = (idx >> 8) % NKSG;
    int bot  = (idx >> 8) / NKSG;               // b*2 + ot
    int ot = bot & 1, b = bot >> 1;
    int o  = ot * 32 + nf * 8 + (lane >> 2);
    int kk = ksg * 8 + (lane & 3) + 4 * r;      // 0..863
    int c  = kk / 27;
    int s  = kk - c * 27;
    float acc = 0.f;
    #pragma unroll
    for (int t = 0; t < TT; t++)
        acc += weight[(o * CIN + c) * TT + t] * stencils[(b * TT + t) * 27 + s];
    g_wf[idx] = f2tf32(acc);
}

__global__ __launch_bounds__(256, 2)
void stencilconv3d_kernel(const float* __restrict__ x,
                          const float* __restrict__ bias,
                          float* __restrict__ out) {
    extern __shared__ uint32_t sm[];
    const uint32_t smb = smem_u32(sm);

    const int h0  = blockIdx.x;   // 0..31 (pair of h rows)
    const int d0  = blockIdx.y;   // 0..31
    const int b   = blockIdx.z;   // 0..3
    const int tid = threadIdx.x;
    const int wid = tid >> 5;     // 0..7
    const int lane = tid & 31;

    // GEMM warp mapping: wid = pt2*2 + ot
    const int pt2 = wid >> 1;     // 0..3 : 32-point tile
    const int ot  = wid & 1;      // 0..1 : 32-cout tile

    // ---- build k -> xs-row-offset table (byte offsets incl. XS_OFF), once ----
    // tbl[ks*4 + j] = { off(k=ks*8+j), off(k+4) }
    if (tid < NKSG) {              // NKSG=108 entries (per-chunk k space, reused all chunks)
        int ks = tid >> 2, j = tid & 3;
        uint32_t offs[2];
        #pragma unroll
        for (int h = 0; h < 2; h++) {
            int k  = ks * 8 + j + 4 * h;   // 0..215
            int cl = k / 27;
            int s  = k - cl * 27;
            int dz = s / 9;
            int s9 = s - dz * 9;
            int hy = s9 / 3;
            int wx = s9 - hy * 3;
            offs[h] = (uint32_t)(XS_OFF + (cl * 12 + dz * 4 + hy) * 68 + wx) * 4u;
        }
        ((uint2*)sm)[tid] = make_uint2(offs[0], offs[1]);
    }

    // per-thread A-frag point offsets (byte), both m-frags same prow
    const int pbase = pt2 * 32;
    const int prow  = pbase >> 6;
    const uint32_t poff0 = (uint32_t)(prow * 68 + (pbase & 63) + (lane >> 2)) * 4u;

    float acc[2][4][4];
    #pragma unroll
    for (int i = 0; i < 2; i++)
        #pragma unroll
        for (int j = 0; j < 4; j++)
            #pragma unroll
            for (int c = 0; c < 4; c++) acc[i][j][c] = 0.f;

    const size_t x_plane = (size_t)DDIM * HDIM * WDIM;
    const int hbase = h0 * 2 - 1;
    // B fragment pointer for this warp: stride per ksg = 64 uint4
    const uint4* gwp = (const uint4*)(g_wf + (((size_t)(b * 2 + ot)) * NKSG * 32 + lane) * 8);

    #pragma unroll 1
    for (int chunk = 0; chunk < 4; chunk++) {
        __syncthreads();   // xs free for reuse (tbl written before 1st sync, read-only after)

        // ---- load x chunk: 8c x (3d x 4h) x 68w, zero-padded, tf32-rounded ----
        const float* xb = x + ((size_t)b * CIN + (size_t)chunk * 8) * x_plane;
        {
            int wx = tid % 68;
            int rr = tid / 68;
            int cl = 0;
            for (int idx = tid; idx < XS_SIZE; idx += 256) {
                int dg = d0 + (rr >> 2) - 1;
                int hg = hbase + (rr & 3);
                int wg = wx - 1;
                float v = 0.f;
                if (wx < 66 && (unsigned)dg < DDIM && (unsigned)hg < HDIM && (unsigned)wg < WDIM)
                    v = xb[((size_t)cl * DDIM + dg) * HDIM * WDIM + (size_t)hg * WDIM + wg];
                sm[XS_OFF + idx] = f2tf32(v);
                // advance by 256 = 3*68 + 52
                wx += 52; rr += 3;
                if (wx >= 68) { wx -= 68; rr++; }
                if (rr >= 12) { rr -= 12; cl++; }
            }
        }
        __syncthreads();

        // ---- GEMM: 27 k-steps of 8 over this chunk's (8c x 27s) ----
        const uint4* gwc = gwp + (size_t)chunk * 27 * 64;
        #pragma unroll 3
        for (int ks = 0; ks < 27; ks++) {
            uint32_t tlo, thi;
            lds64(smb + (uint32_t)(TBL_OFF + ks * 4 + (lane & 3)) * 8u, tlo, thi);
            uint32_t alo = smb + tlo + poff0;
            uint32_t ahi = smb + thi + poff0;
            // mf0: rows p..p+15 ; mf1: +64B (16 points)
            uint32_t a0[2], a1[2], a2[2], a3[2];
            #pragma unroll
            for (int mf = 0; mf < 2; mf++) {
                uint32_t d = (uint32_t)mf * 64u;
                a0[mf] = lds32(alo + d);
                a1[mf] = lds32(alo + d + 32u);
                a2[mf] = lds32(ahi + d);
                a3[mf] = lds32(ahi + d + 32u);
            }
            uint4 b01 = __ldg(&gwc[ks * 64]);
            uint4 b23 = __ldg(&gwc[ks * 64 + 1]);
            mma_tf32(acc[0][0], a0[0], a1[0], a2[0], a3[0], b01.x, b01.y);
            mma_tf32(acc[1][0], a0[1], a1[1], a2[1], a3[1], b01.x, b01.y);
            mma_tf32(acc[0][1], a0[0], a1[0], a2[0], a3[0], b01.z, b01.w);
            mma_tf32(acc[1][1], a0[1], a1[1], a2[1], a3[1], b01.z, b01.w);
            mma_tf32(acc[0][2], a0[0], a1[0], a2[0], a3[0], b23.x, b23.y);
            mma_tf32(acc[1][2], a0[1], a1[1], a2[1], a3[1], b23.x, b23.y);
            mma_tf32(acc[0][3], a0[0], a1[0], a2[0], a3[0], b23.z, b23.w);
            mma_tf32(acc[1][3], a0[1], a1[1], a2[1], a3[1], b23.z, b23.w);
        }
    }

    // ---- epilogue: registers -> gmem, + bias ----
    {
        const size_t ostride = (size_t)DDIM * HDIM * WDIM;
        #pragma unroll
        for (int nf = 0; nf < 4; nf++) {
            int o0 = ot * 32 + nf * 8 + (lane & 3) * 2;
            float bv0 = __ldg(&bias[o0]);
            float bv1 = __ldg(&bias[o0 + 1]);
            #pragma unroll
            for (int mf = 0; mf < 2; mf++) {
                #pragma unroll
                for (int c = 0; c < 4; c++) {
                    float s = acc[mf][nf][c];
                    int o = o0 + (c & 1);
                    int p = pt2 * 32 + mf * 16 + (lane >> 2) + ((c >> 1) & 1) * 8;
                    int h = h0 * 2 + (p >> 6);
                    int w = p & 63;
                    out[((size_t)b * COUT + o) * ostride
                        + (size_t)d0 * HDIM * WDIM + (size_t)h * WDIM + w]
                        = s + ((c & 1) ? bv1 : bv0);
                }
            }
        }
    }
}

extern "C" void kernel_launch(void* const* d_in, const int* in_sizes, int n_in,
                              void* d_out, int out_size) {
    const float* x        = (const float*)d_in[0];
    const float* stencils = (const float*)d_in[1];
    const float* weight   = (const float*)d_in[2];
    const float* bias     = (const float*)d_in[3];
    float* out = (float*)d_out;

    init_wf_kernel<<<864, 256>>>(weight, stencils);

    cudaFuncSetAttribute(stencilconv3d_kernel,
                         cudaFuncAttributeMaxDynamicSharedMemorySize, SMEM_BYTES);
    dim3 grid(HDIM / 2, DDIM, 4);   // 32 x 32 x 4 = 4096 blocks
    stencilconv3d_kernel<<<grid, 256, SMEM_BYTES>>>(x, bias, out);
}

// round 9
// speedup vs baseline: 1.9531x; 1.9531x over previous
#include <cuda_runtime.h>
#include <cuda_fp16.h>
#include <cstdint>

#define CIN   32
#define COUT  64
#define TT    8
#define DDIM  32
#define HDIM  64
#define WDIM  64

// xs2: [cp(8)][row(18 = 3d x 6h)][wc(68)] half2 words (channels 2cp,2cp+1 packed)
#define CPSTRIDE (18 * 68)             // 1224 words per cp plane
#define XS2_SIZE (8 * CPSTRIDE)        // 9792 words
#define SMEM_BYTES (XS2_SIZE * 4)      // 39168 B

// fused weights, fp16 frag layout: g_w2[((b*2+cg)*27+s)*32+lane][16 u32]
// word r = nf*2+half : half2{ w'[o][cA], w'[o][cA+1] },
//   o = nf*8 + (lane>>2), cA = cg*16 + half*8 + 2*(lane&3)
__device__ uint32_t g_w2[4 * 2 * 27 * 32 * 16];   // 110592 u32

__device__ __forceinline__ uint32_t smem_u32(const void* p) {
    uint32_t a;
    asm("{ .reg .u64 t; cvta.to.shared.u64 t, %1; cvt.u32.u64 %0, t; }" : "=r"(a) : "l"(p));
    return a;
}
__device__ __forceinline__ uint32_t lds32(uint32_t a) {
    uint32_t v; asm volatile("ld.shared.b32 %0, [%1];" : "=r"(v) : "r"(a)); return v;
}
__device__ __forceinline__ void mma_f16(float* c,
                                        uint32_t a0, uint32_t a1, uint32_t a2, uint32_t a3,
                                        uint32_t b0, uint32_t b1) {
    asm volatile("mma.sync.aligned.m16n8k16.row.col.f32.f16.f16.f32 "
                 "{%0,%1,%2,%3}, {%4,%5,%6,%7}, {%8,%9}, {%0,%1,%2,%3};"
                 : "+f"(c[0]), "+f"(c[1]), "+f"(c[2]), "+f"(c[3])
                 : "r"(a0), "r"(a1), "r"(a2), "r"(a3), "r"(b0), "r"(b1));
}

// ---------- init: w'[b,o,c,s] = sum_t weight[o,c,t]*stencils[b,t,s] -> fp16 frags ----------
__global__ void init_w2_kernel(const float* __restrict__ weight,
                               const float* __restrict__ stencils) {
    int idx  = blockIdx.x * 256 + threadIdx.x;   // 0 .. 110591
    int r    = idx & 15;
    int lane = (idx >> 4) & 31;
    int s    = (idx >> 9) % 27;
    int rest = (idx >> 9) / 27;                  // b*2 + cg
    int cg = rest & 1, b = rest >> 1;
    int nf = r >> 1, half = r & 1;
    int o  = nf * 8 + (lane >> 2);
    int cA = cg * 16 + half * 8 + 2 * (lane & 3);
    float va = 0.f, vb = 0.f;
    #pragma unroll
    for (int t = 0; t < TT; t++) {
        float st = stencils[(b * TT + t) * 27 + s];
        va += weight[(o * CIN + cA) * TT + t] * st;
        vb += weight[(o * CIN + cA + 1) * TT + t] * st;
    }
    __half2 h = __floats2half2_rn(va, vb);
    g_w2[idx] = *reinterpret_cast<uint32_t*>(&h);
}

__global__ __launch_bounds__(256, 2)
void stencilconv3d_kernel(const float* __restrict__ x,
                          const float* __restrict__ bias,
                          float* __restrict__ out) {
    extern __shared__ uint32_t sm[];
    const uint32_t smb = smem_u32(sm);

    const int h0  = blockIdx.x;   // 0..15 (4 output h rows)
    const int d0  = blockIdx.y;   // 0..31
    const int bz  = blockIdx.z;   // 0..3
    const int tid = threadIdx.x;
    const int pt  = tid >> 5;     // warp = 32-point tile, 0..7
    const int lane = tid & 31;

    const int hl    = pt >> 1;            // local output h row 0..3
    const int wbase = (pt & 1) * 32;      // w half

    // thread-invariant part of A-frag address (bytes)
    const uint32_t poff = smb + (uint32_t)((lane & 3) * CPSTRIDE + hl * 68
                                           + wbase + (lane >> 2)) * 4u;

    float acc[2][8][4];
    #pragma unroll
    for (int i = 0; i < 2; i++)
        #pragma unroll
        for (int j = 0; j < 8; j++)
            #pragma unroll
            for (int c = 0; c < 4; c++) acc[i][j][c] = 0.f;

    const size_t x_plane = (size_t)DDIM * HDIM * WDIM;
    const int hbase = h0 * 4 - 1;

    #pragma unroll 1
    for (int cg = 0; cg < 2; cg++) {
        __syncthreads();   // xs2 free for reuse

        // ---- load x: 16 channels as 8 half2 planes, 18 rows x 68 w, zero-padded ----
        const float* xc = x + ((size_t)bz * CIN + (size_t)cg * 16) * x_plane;
        {
            int wc = tid % 68;
            int rw = tid / 68;           // 0..3
            int hq = rw, dz = 0, cp = 0;
            for (int idx = tid; idx < XS2_SIZE; idx += 256) {
                int dg = d0 + dz - 1;
                int hg = hbase + hq;
                int wg = wc - 1;
                float v0 = 0.f, v1 = 0.f;
                if (wc < 66 && (unsigned)dg < DDIM && (unsigned)hg < HDIM && (unsigned)wg < WDIM) {
                    const float* p0 = xc + (size_t)(2 * cp) * x_plane
                                    + ((size_t)dg * HDIM + hg) * WDIM + wg;
                    v0 = p0[0];
                    v1 = p0[x_plane];
                }
                __half2 h = __floats2half2_rn(v0, v1);
                sm[idx] = *reinterpret_cast<uint32_t*>(&h);
                // advance by 256 = 3*68 + 52
                wc += 52; hq += 3;
                if (wc >= 68) { wc -= 68; hq++; }
                if (hq >= 6)  { hq -= 6; dz++; }
                if (dz >= 3)  { dz -= 3; cp++; }
            }
        }
        __syncthreads();

        // ---- GEMM: 27 k16-steps (one per stencil offset s), fully unrolled ----
        const uint4* wp = (const uint4*)g_w2
                        + ((size_t)((bz * 2 + cg) * 27) * 32 + lane) * 4;
        #pragma unroll
        for (int s = 0; s < 27; s++) {
            const int rowoff = (((s / 9) * 6 + ((s % 9) / 3)) * 68 + (s % 3)) * 4;
            uint32_t af[2][4];
            #pragma unroll
            for (int mf = 0; mf < 2; mf++) {
                uint32_t ab = poff + (uint32_t)rowoff + (uint32_t)mf * 64u;
                af[mf][0] = lds32(ab);
                af[mf][1] = lds32(ab + 32u);                 // +8 points
                af[mf][2] = lds32(ab + 4u * CPSTRIDE * 4u);  // +4 cp planes (k+8)
                af[mf][3] = lds32(ab + 4u * CPSTRIDE * 4u + 32u);
            }
            const uint4* wps = wp + (size_t)s * 128;         // 32 lanes * 4 uint4
            uint4 q0 = __ldg(wps + 0);
            uint4 q1 = __ldg(wps + 1);
            uint4 q2 = __ldg(wps + 2);
            uint4 q3 = __ldg(wps + 3);
            mma_f16(acc[0][0], af[0][0], af[0][1], af[0][2], af[0][3], q0.x, q0.y);
            mma_f16(acc[1][0], af[1][0], af[1][1], af[1][2], af[1][3], q0.x, q0.y);
            mma_f16(acc[0][1], af[0][0], af[0][1], af[0][2], af[0][3], q0.z, q0.w);
            mma_f16(acc[1][1], af[1][0], af[1][1], af[1][2], af[1][3], q0.z, q0.w);
            mma_f16(acc[0][2], af[0][0], af[0][1], af[0][2], af[0][3], q1.x, q1.y);
            mma_f16(acc[1][2], af[1][0], af[1][1], af[1][2], af[1][3], q1.x, q1.y);
            mma_f16(acc[0][3], af[0][0], af[0][1], af[0][2], af[0][3], q1.z, q1.w);
            mma_f16(acc[1][3], af[1][0], af[1][1], af[1][2], af[1][3], q1.z, q1.w);
            mma_f16(acc[0][4], af[0][0], af[0][1], af[0][2], af[0][3], q2.x, q2.y);
            mma_f16(acc[1][4], af[1][0], af[1][1], af[1][2], af[1][3], q2.x, q2.y);
            mma_f16(acc[0][5], af[0][0], af[0][1], af[0][2], af[0][3], q2.z, q2.w);
            mma_f16(acc[1][5], af[1][0], af[1][1], af[1][2], af[1][3], q2.z, q2.w);
            mma_f16(acc[0][6], af[0][0], af[0][1], af[0][2], af[0][3], q3.x, q3.y);
            mma_f16(acc[1][6], af[1][0], af[1][1], af[1][2], af[1][3], q3.x, q3.y);
            mma_f16(acc[0][7], af[0][0], af[0][1], af[0][2], af[0][3], q3.z, q3.w);
            mma_f16(acc[1][7], af[1][0], af[1][1], af[1][2], af[1][3], q3.z, q3.w);
        }
    }

    // ---- epilogue: registers -> gmem, + bias ----
    {
        const size_t ostride = (size_t)DDIM * HDIM * WDIM;
        #pragma unroll
        for (int nf = 0; nf < 8; nf++) {
            int o0 = nf * 8 + (lane & 3) * 2;
            float bv0 = __ldg(&bias[o0]);
            float bv1 = __ldg(&bias[o0 + 1]);
            #pragma unroll
            for (int mf = 0; mf < 2; mf++) {
                #pragma unroll
                for (int cc = 0; cc < 4; cc++) {
                    float sv = acc[mf][nf][cc];
                    int o = o0 + (cc & 1);
                    int p = pt * 32 + mf * 16 + (lane >> 2) + ((cc >> 1) & 1) * 8;
                    int h = h0 * 4 + (p >> 6);
                    int w = p & 63;
                    out[((size_t)bz * COUT + o) * ostride
                        + (size_t)d0 * HDIM * WDIM + (size_t)h * WDIM + w]
                        = sv + ((cc & 1) ? bv1 : bv0);
                }
            }
        }
    }
}

extern "C" void kernel_launch(void* const* d_in, const int* in_sizes, int n_in,
                              void* d_out, int out_size) {
    const float* x        = (const float*)d_in[0];
    const float* stencils = (const float*)d_in[1];
    const float* weight   = (const float*)d_in[2];
    const float* bias     = (const float*)d_in[3];
    float* out = (float*)d_out;

    init_w2_kernel<<<432, 256>>>(weight, stencils);

    cudaFuncSetAttribute(stencilconv3d_kernel,
                         cudaFuncAttributeMaxDynamicSharedMemorySize, SMEM_BYTES);
    dim3 grid(HDIM / 4, DDIM, 4);   // 16 x 32 x 4 = 2048 blocks
    stencilconv3d_kernel<<<grid, 256, SMEM_BYTES>>>(x, bias, out);
}

// round 10
// speedup vs baseline: 2.0707x; 1.0602x over previous
#include <cuda_runtime.h>
#include <cuda_fp16.h>
#include <cstdint>

#define CIN   32
#define COUT  64
#define TT    8
#define DDIM  32
#define HDIM  64
#define WDIM  64

// xs2: [cp(8)][row(18 = 3d x 6h)][wc(68)] half2 words (channels 2cp,2cp+1 packed)
#define CPSTRIDE (18 * 68)             // 1224 words per cp plane
#define XS2_SIZE (8 * CPSTRIDE)        // 9792 words
#define SMEM_BYTES (XS2_SIZE * 4)      // 39168 B

// fused weights, fp16 frag layout: g_w2[((b*2+cg)*27+s)*32+lane][16 u32]
// word r = nf*2+half : half2{ w'[o][cA], w'[o][cA+1] },
//   o = nf*8 + (lane>>2), cA = cg*16 + half*8 + 2*(lane&3)
__device__ uint32_t g_w2[4 * 2 * 27 * 32 * 16];   // 110592 u32

__device__ __forceinline__ uint32_t smem_u32(const void* p) {
    uint32_t a;
    asm("{ .reg .u64 t; cvta.to.shared.u64 t, %1; cvt.u32.u64 %0, t; }" : "=r"(a) : "l"(p));
    return a;
}
__device__ __forceinline__ uint32_t lds32(uint32_t a) {
    uint32_t v; asm volatile("ld.shared.b32 %0, [%1];" : "=r"(v) : "r"(a)); return v;
}
__device__ __forceinline__ void mma_f16(float* c,
                                        uint32_t a0, uint32_t a1, uint32_t a2, uint32_t a3,
                                        uint32_t b0, uint32_t b1) {
    asm volatile("mma.sync.aligned.m16n8k16.row.col.f32.f16.f16.f32 "
                 "{%0,%1,%2,%3}, {%4,%5,%6,%7}, {%8,%9}, {%0,%1,%2,%3};"
                 : "+f"(c[0]), "+f"(c[1]), "+f"(c[2]), "+f"(c[3])
                 : "r"(a0), "r"(a1), "r"(a2), "r"(a3), "r"(b0), "r"(b1));
}

// ---------- init: w'[b,o,c,s] = sum_t weight[o,c,t]*stencils[b,t,s] -> fp16 frags ----------
__global__ void init_w2_kernel(const float* __restrict__ weight,
                               const float* __restrict__ stencils) {
    int idx  = blockIdx.x * 256 + threadIdx.x;   // 0 .. 110591
    int r    = idx & 15;
    int lane = (idx >> 4) & 31;
    int s    = (idx >> 9) % 27;
    int rest = (idx >> 9) / 27;                  // b*2 + cg
    int cg = rest & 1, b = rest >> 1;
    int nf = r >> 1, half = r & 1;
    int o  = nf * 8 + (lane >> 2);
    int cA = cg * 16 + half * 8 + 2 * (lane & 3);
    float va = 0.f, vb = 0.f;
    #pragma unroll
    for (int t = 0; t < TT; t++) {
        float st = stencils[(b * TT + t) * 27 + s];
        va += weight[(o * CIN + cA) * TT + t] * st;
        vb += weight[(o * CIN + cA + 1) * TT + t] * st;
    }
    __half2 h = __floats2half2_rn(va, vb);
    g_w2[idx] = *reinterpret_cast<uint32_t*>(&h);
}

__global__ __launch_bounds__(128, 2)
void stencilconv3d_kernel(const float* __restrict__ x,
                          const float* __restrict__ bias,
                          float* __restrict__ out) {
    extern __shared__ uint32_t sm[];
    const uint32_t smb = smem_u32(sm);

    const int h0  = blockIdx.x;   // 0..15 (4 output h rows)
    const int d0  = blockIdx.y;   // 0..31
    const int bz  = blockIdx.z;   // 0..3
    const int tid = threadIdx.x;
    const int wid = tid >> 5;     // 0..3 : warp = one full h row (64 w points)
    const int lane = tid & 31;

    // thread-invariant part of A-frag address (bytes); warp's h row = wid
    const uint32_t poff = smb + (uint32_t)((lane & 3) * CPSTRIDE + wid * 68
                                           + (lane >> 2)) * 4u;

    float acc[4][8][4];           // [m-frag(16 w each)][n-frag(8 o)][c]
    #pragma unroll
    for (int i = 0; i < 4; i++)
        #pragma unroll
        for (int j = 0; j < 8; j++)
            #pragma unroll
            for (int c = 0; c < 4; c++) acc[i][j][c] = 0.f;

    const size_t x_plane = (size_t)DDIM * HDIM * WDIM;
    const int hbase = h0 * 4 - 1;

    #pragma unroll 1
    for (int cg = 0; cg < 2; cg++) {
        __syncthreads();   // xs2 free for reuse

        // ---- load x: 16 channels as 8 half2 planes, 18 rows x 68 w, zero-padded ----
        const float* xc = x + ((size_t)bz * CIN + (size_t)cg * 16) * x_plane;
        {
            int wc = tid % 68;
            int hq = tid / 68;           // 0..1
            int dz = 0, cp = 0;
            for (int idx = tid; idx < XS2_SIZE; idx += 128) {
                int dg = d0 + dz - 1;
                int hg = hbase + hq;
                int wg = wc - 1;
                float v0 = 0.f, v1 = 0.f;
                if (wc < 66 && (unsigned)dg < DDIM && (unsigned)hg < HDIM && (unsigned)wg < WDIM) {
                    const float* p0 = xc + (size_t)(2 * cp) * x_plane
                                    + ((size_t)dg * HDIM + hg) * WDIM + wg;
                    v0 = p0[0];
                    v1 = p0[x_plane];
                }
                __half2 h = __floats2half2_rn(v0, v1);
                sm[idx] = *reinterpret_cast<uint32_t*>(&h);
                // advance by 128 = 1*68 + 60
                wc += 60; hq += 1;
                if (wc >= 68) { wc -= 68; hq++; }
                if (hq >= 6)  { hq -= 6; dz++; }
                if (dz >= 3)  { dz -= 3; cp++; }
            }
        }
        __syncthreads();

        // ---- GEMM: 27 k16-steps (one per stencil offset s), fully unrolled ----
        const uint4* wp = (const uint4*)g_w2
                        + ((size_t)((bz * 2 + cg) * 27) * 32 + lane) * 4;
        #pragma unroll
        for (int s = 0; s < 27; s++) {
            const int rowoff = (((s / 9) * 6 + ((s % 9) / 3)) * 68 + (s % 3)) * 4;
            uint32_t af[4][4];
            #pragma unroll
            for (int mf = 0; mf < 4; mf++) {
                uint32_t ab = poff + (uint32_t)rowoff + (uint32_t)mf * 64u;
                af[mf][0] = lds32(ab);
                af[mf][1] = lds32(ab + 32u);                 // +8 w points
                af[mf][2] = lds32(ab + 4u * CPSTRIDE * 4u);  // +4 cp planes (k+8)
                af[mf][3] = lds32(ab + 4u * CPSTRIDE * 4u + 32u);
            }
            const uint4* wps = wp + (size_t)s * 128;         // 32 lanes * 4 uint4
            uint4 q0 = __ldg(wps + 0);
            uint4 q1 = __ldg(wps + 1);
            uint4 q2 = __ldg(wps + 2);
            uint4 q3 = __ldg(wps + 3);
            #pragma unroll
            for (int mf = 0; mf < 4; mf++) {
                mma_f16(acc[mf][0], af[mf][0], af[mf][1], af[mf][2], af[mf][3], q0.x, q0.y);
                mma_f16(acc[mf][1], af[mf][0], af[mf][1], af[mf][2], af[mf][3], q0.z, q0.w);
                mma_f16(acc[mf][2], af[mf][0], af[mf][1], af[mf][2], af[mf][3], q1.x, q1.y);
                mma_f16(acc[mf][3], af[mf][0], af[mf][1], af[mf][2], af[mf][3], q1.z, q1.w);
                mma_f16(acc[mf][4], af[mf][0], af[mf][1], af[mf][2], af[mf][3], q2.x, q2.y);
                mma_f16(acc[mf][5], af[mf][0], af[mf][1], af[mf][2], af[mf][3], q2.z, q2.w);
                mma_f16(acc[mf][6], af[mf][0], af[mf][1], af[mf][2], af[mf][3], q3.x, q3.y);
                mma_f16(acc[mf][7], af[mf][0], af[mf][1], af[mf][2], af[mf][3], q3.z, q3.w);
            }
        }
    }

    // ---- epilogue: registers -> gmem, + bias ----
    {
        const size_t ostride = (size_t)DDIM * HDIM * WDIM;
        const int h = h0 * 4 + wid;
        const size_t obase = (size_t)bz * COUT * ostride
                           + (size_t)d0 * HDIM * WDIM + (size_t)h * WDIM;
        #pragma unroll
        for (int nf = 0; nf < 8; nf++) {
            int o0 = nf * 8 + (lane & 3) * 2;
            float bv0 = __ldg(&bias[o0]);
            float bv1 = __ldg(&bias[o0 + 1]);
            #pragma unroll
            for (int mf = 0; mf < 4; mf++) {
                #pragma unroll
                for (int cc = 0; cc < 4; cc++) {
                    float sv = acc[mf][nf][cc];
                    int o = o0 + (cc & 1);
                    int w = mf * 16 + (lane >> 2) + ((cc >> 1) & 1) * 8;
                    out[obase + (size_t)o * ostride + w]
                        = sv + ((cc & 1) ? bv1 : bv0);
                }
            }
        }
    }
}

extern "C" void kernel_launch(void* const* d_in, const int* in_sizes, int n_in,
                              void* d_out, int out_size) {
    const float* x        = (const float*)d_in[0];
    const float* stencils = (const float*)d_in[1];
    const float* weight   = (const float*)d_in[2];
    const float* bias     = (const float*)d_in[3];
    float* out = (float*)d_out;

    init_w2_kernel<<<432, 256>>>(weight, stencils);

    cudaFuncSetAttribute(stencilconv3d_kernel,
                         cudaFuncAttributeMaxDynamicSharedMemorySize, SMEM_BYTES);
    dim3 grid(HDIM / 4, DDIM, 4);   // 16 x 32 x 4 = 2048 blocks
    stencilconv3d_kernel<<<grid, 128, SMEM_BYTES>>>(x, bias, out);
}

// round 11
// speedup vs baseline: 2.4391x; 1.1779x over previous
#include <cuda_runtime.h>
#include <cuda_fp16.h>
#include <cstdint>

#define CIN   32
#define COUT  64
#define TT    8
#define DDIM  32
#define HDIM  64
#define WDIM  64

// xs2: [cp(8)][row(18 = 3d x 6h)][wc(68)] half2 words (channels 2cp,2cp+1 packed)
#define CPSTRIDE (18 * 68)             // 1224 words per cp plane
#define XS2_SIZE (8 * CPSTRIDE)        // 9792 words
#define SMEM_BYTES (XS2_SIZE * 4)      // 39168 B -> 2 blocks/SM

// fused weights, fp16 frag layout: g_w2[((b*2+cg)*27+s)*32+lane][16 u32]
// word r = nf*2+half : half2{ w'[o][cA], w'[o][cA+1] },
//   o = nf*8 + (lane>>2), cA = cg*16 + half*8 + 2*(lane&3)
__device__ uint32_t g_w2[4 * 2 * 27 * 32 * 16];   // 110592 u32

__device__ __forceinline__ uint32_t smem_u32(const void* p) {
    uint32_t a;
    asm("{ .reg .u64 t; cvta.to.shared.u64 t, %1; cvt.u32.u64 %0, t; }" : "=r"(a) : "l"(p));
    return a;
}
__device__ __forceinline__ uint32_t lds32(uint32_t a) {
    uint32_t v; asm volatile("ld.shared.b32 %0, [%1];" : "=r"(v) : "r"(a)); return v;
}
__device__ __forceinline__ void mma_f16(float* c,
                                        uint32_t a0, uint32_t a1, uint32_t a2, uint32_t a3,
                                        uint32_t b0, uint32_t b1) {
    asm volatile("mma.sync.aligned.m16n8k16.row.col.f32.f16.f16.f32 "
                 "{%0,%1,%2,%3}, {%4,%5,%6,%7}, {%8,%9}, {%0,%1,%2,%3};"
                 : "+f"(c[0]), "+f"(c[1]), "+f"(c[2]), "+f"(c[3])
                 : "r"(a0), "r"(a1), "r"(a2), "r"(a3), "r"(b0), "r"(b1));
}

// ---------- init: w'[b,o,c,s] = sum_t weight[o,c,t]*stencils[b,t,s] -> fp16 frags ----------
__global__ void init_w2_kernel(const float* __restrict__ weight,
                               const float* __restrict__ stencils) {
    int idx  = blockIdx.x * 256 + threadIdx.x;   // 0 .. 110591
    int r    = idx & 15;
    int lane = (idx >> 4) & 31;
    int s    = (idx >> 9) % 27;
    int rest = (idx >> 9) / 27;                  // b*2 + cg
    int cg = rest & 1, b = rest >> 1;
    int nf = r >> 1, half = r & 1;
    int o  = nf * 8 + (lane >> 2);
    int cA = cg * 16 + half * 8 + 2 * (lane & 3);
    float va = 0.f, vb = 0.f;
    #pragma unroll
    for (int t = 0; t < TT; t++) {
        float st = stencils[(b * TT + t) * 27 + s];
        va += weight[(o * CIN + cA) * TT + t] * st;
        vb += weight[(o * CIN + cA + 1) * TT + t] * st;
    }
    __half2 h = __floats2half2_rn(va, vb);
    g_w2[idx] = *reinterpret_cast<uint32_t*>(&h);
}

__global__ __launch_bounds__(256, 2)
void stencilconv3d_kernel(const float* __restrict__ x,
                          const float* __restrict__ bias,
                          float* __restrict__ out) {
    extern __shared__ uint32_t sm[];
    const uint32_t smb = smem_u32(sm);

    const int h0  = blockIdx.x;   // 0..15 (4 output h rows)
    const int d0  = blockIdx.y;   // 0..31
    const int bz  = blockIdx.z;   // 0..3
    const int tid = threadIdx.x;
    const int wid = tid >> 5;     // 0..7
    const int lane = tid & 31;

    // warp mapping: hl = h row (0..3), oh = o half (0..1)
    const int hl = wid >> 1;
    const int oh = wid & 1;

    // thread-invariant part of A-frag address (bytes); warp's h row = hl
    const uint32_t poff = smb + (uint32_t)((lane & 3) * CPSTRIDE + hl * 68
                                           + (lane >> 2)) * 4u;

    float acc[4][4][4];           // [m-frag(16 w each)][n-frag(8 o, this half)][c]
    #pragma unroll
    for (int i = 0; i < 4; i++)
        #pragma unroll
        for (int j = 0; j < 4; j++)
            #pragma unroll
            for (int c = 0; c < 4; c++) acc[i][j][c] = 0.f;

    const size_t x_plane = (size_t)DDIM * HDIM * WDIM;
    const int hbase = h0 * 4 - 1;

    #pragma unroll 1
    for (int cg = 0; cg < 2; cg++) {
        __syncthreads();   // xs2 free for reuse

        // ---- load x: 16 channels as 8 half2 planes, 18 rows x 68 w, zero-padded ----
        const float* xc = x + ((size_t)bz * CIN + (size_t)cg * 16) * x_plane;
        {
            int wc = tid % 68;
            int hq = tid / 68;           // 0..3
            int dz = 0, cp = 0;
            for (int idx = tid; idx < XS2_SIZE; idx += 256) {
                int dg = d0 + dz - 1;
                int hg = hbase + hq;
                int wg = wc - 1;
                float v0 = 0.f, v1 = 0.f;
                if (wc < 66 && (unsigned)dg < DDIM && (unsigned)hg < HDIM && (unsigned)wg < WDIM) {
                    const float* p0 = xc + (size_t)(2 * cp) * x_plane
                                    + ((size_t)dg * HDIM + hg) * WDIM + wg;
                    v0 = p0[0];
                    v1 = p0[x_plane];
                }
                __half2 h = __floats2half2_rn(v0, v1);
                sm[idx] = *reinterpret_cast<uint32_t*>(&h);
                // advance by 256 = 3*68 + 52
                wc += 52; hq += 3;
                if (wc >= 68) { wc -= 68; hq++; }
                if (hq >= 6)  { hq -= 6; dz++; }
                if (dz >= 3)  { dz -= 3; cp++; }
            }
        }
        __syncthreads();

        // ---- GEMM: 27 k16-steps (one per stencil offset s), fully unrolled ----
        const uint4* wp = (const uint4*)g_w2
                        + ((size_t)((bz * 2 + cg) * 27) * 32 + lane) * 4 + oh * 2;
        #pragma unroll
        for (int s = 0; s < 27; s++) {
            const int rowoff = (((s / 9) * 6 + ((s % 9) / 3)) * 68 + (s % 3)) * 4;
            uint32_t af[4][4];
            #pragma unroll
            for (int mf = 0; mf < 4; mf++) {
                uint32_t ab = poff + (uint32_t)rowoff + (uint32_t)mf * 64u;
                af[mf][0] = lds32(ab);
                af[mf][1] = lds32(ab + 32u);                 // +8 w points
                af[mf][2] = lds32(ab + 4u * CPSTRIDE * 4u);  // +4 cp planes (k+8)
                af[mf][3] = lds32(ab + 4u * CPSTRIDE * 4u + 32u);
            }
            const uint4* wps = wp + (size_t)s * 128;         // 32 lanes * 4 uint4
            uint4 q0 = __ldg(wps + 0);      // nf_local 0,1
            uint4 q1 = __ldg(wps + 1);      // nf_local 2,3
            #pragma unroll
            for (int mf = 0; mf < 4; mf++) {
                mma_f16(acc[mf][0], af[mf][0], af[mf][1], af[mf][2], af[mf][3], q0.x, q0.y);
                mma_f16(acc[mf][1], af[mf][0], af[mf][1], af[mf][2], af[mf][3], q0.z, q0.w);
                mma_f16(acc[mf][2], af[mf][0], af[mf][1], af[mf][2], af[mf][3], q1.x, q1.y);
                mma_f16(acc[mf][3], af[mf][0], af[mf][1], af[mf][2], af[mf][3], q1.z, q1.w);
            }
        }
    }

    // ---- epilogue: registers -> gmem, + bias ----
    {
        const size_t ostride = (size_t)DDIM * HDIM * WDIM;
        const int h = h0 * 4 + hl;
        const size_t obase = (size_t)bz * COUT * ostride
                           + (size_t)d0 * HDIM * WDIM + (size_t)h * WDIM;
        #pragma unroll
        for (int nf = 0; nf < 4; nf++) {
            int o0 = oh * 32 + nf * 8 + (lane & 3) * 2;
            float bv0 = __ldg(&bias[o0]);
            float bv1 = __ldg(&bias[o0 + 1]);
            #pragma unroll
            for (int mf = 0; mf < 4; mf++) {
                #pragma unroll
                for (int cc = 0; cc < 4; cc++) {
                    float sv = acc[mf][nf][cc];
                    int o = o0 + (cc & 1);
                    int w = mf * 16 + (lane >> 2) + ((cc >> 1) & 1) * 8;
                    out[obase + (size_t)o * ostride + w]
                        = sv + ((cc & 1) ? bv1 : bv0);
                }
            }
        }
    }
}

extern "C" void kernel_launch(void* const* d_in, const int* in_sizes, int n_in,
                              void* d_out, int out_size) {
    const float* x        = (const float*)d_in[0];
    const float* stencils = (const float*)d_in[1];
    const float* weight   = (const float*)d_in[2];
    const float* bias     = (const float*)d_in[3];
    float* out = (float*)d_out;

    init_w2_kernel<<<432, 256>>>(weight, stencils);

    cudaFuncSetAttribute(stencilconv3d_kernel,
                         cudaFuncAttributeMaxDynamicSharedMemorySize, SMEM_BYTES);
    dim3 grid(HDIM / 4, DDIM, 4);   // 16 x 32 x 4 = 2048 blocks
    stencilconv3d_kernel<<<grid, 256, SMEM_BYTES>>>(x, bias, out);
}